// round 1
// baseline (speedup 1.0000x reference)
#include <cuda_runtime.h>
#include <math.h>

#define D_INF   128
#define D_OUTF  128
#define KNOTS   64
#define NBATCH  4096
#define EPSF    1e-12f
#define BPB     8      // batches per block (1 per warp)

// Precomputed transposed tables: [i][k][o], contiguous in o.
__device__ float g_ct[D_INF * KNOTS * D_OUTF];
__device__ float g_dt[D_INF * KNOTS * D_OUTF];

// ---------------------------------------------------------------------------
// Kernel 1: transpose coeffs -> g_ct and compute PCHIP slopes -> g_dt.
// block = 128 threads (o), grid = 128 (i). Writes coalesced over o.
// Replicates the reference formula bit-for-bit in fp32 (incl. EPS terms).
// ---------------------------------------------------------------------------
__global__ __launch_bounds__(128) void kan_preprocess(
    const float* __restrict__ coeffs,   // [D_OUT][D_IN][K]
    const float* __restrict__ knots)    // [K]
{
    __shared__ float h_s[KNOTS - 1];
    const int o = threadIdx.x;
    const int i = blockIdx.x;
    if (o < KNOTS - 1) h_s[o] = knots[o + 1] - knots[o];
    __syncthreads();

    const float* y = coeffs + (o * D_INF + i) * KNOTS;
    float* ct = g_ct + i * (KNOTS * D_OUTF) + o;
    float* dt = g_dt + i * (KNOTS * D_OUTF) + o;

    float y0v = y[0];
    float y1v = y[1];
    ct[0]       = y0v;
    ct[D_OUTF]  = y1v;

    float delta_prev = (y1v - y0v) / (h_s[0] + EPSF);   // delta[0]
    const float delta0 = delta_prev;
    float delta1  = 0.f;
    float delta61 = 0.f;
    float prev_y  = y1v;

    #pragma unroll 1
    for (int k = 1; k <= KNOTS - 2; ++k) {
        float ynext = y[k + 1];
        ct[(k + 1) * D_OUTF] = ynext;
        float delta_cur = (ynext - prev_y) / (h_s[k] + EPSF);  // delta[k]
        if (k == 1)         delta1  = delta_cur;
        if (k == KNOTS - 3) delta61 = delta_cur;               // delta[K-3]
        float h0 = h_s[k - 1], h1 = h_s[k];
        float w1 = 2.f * h1 + h0;
        float w2 = h1 + 2.f * h0;
        float dd = 0.f;
        if (delta_prev * delta_cur > 0.f) {
            float denom = w1 / (delta_prev + EPSF) + w2 / (delta_cur + EPSF);
            dd = (w1 + w2) / (denom + EPSF);
        }
        dt[k * D_OUTF] = dd;
        delta_prev = delta_cur;
        prev_y = ynext;
    }
    const float delta62 = delta_prev;  // delta[K-2]

    // d_first (with PCHIP endpoint limiter)
    float df = ((2.f * h_s[0] + h_s[1]) * delta0 - h_s[0] * delta1) /
               (h_s[0] + h_s[1] + EPSF);
    df = (df * delta0 <= 0.f) ? 0.f : df;
    df = (fabsf(df) > 3.f * fabsf(delta0)) ? 3.f * delta0 : df;
    dt[0] = df;

    // d_last
    float dl = ((2.f * h_s[KNOTS - 2] + h_s[KNOTS - 3]) * delta62 -
                h_s[KNOTS - 2] * delta61) /
               (h_s[KNOTS - 2] + h_s[KNOTS - 3] + EPSF);
    dl = (dl * delta62 <= 0.f) ? 0.f : dl;
    dl = (fabsf(dl) > 3.f * fabsf(delta62)) ? 3.f * delta62 : dl;
    dt[(KNOTS - 1) * D_OUTF] = dl;
}

// ---------------------------------------------------------------------------
// Kernel 2: main evaluation.
// block = 256 threads = 8 warps; warp <-> batch, lane <-> o-quad (float4).
// Phase 1: all 256 threads precompute (idx, 4 weights) for 8 batches x 128 i
//          into smem. Phase 2: warp-uniform-idx gathers, coalesced LDG.128.
// ---------------------------------------------------------------------------
__global__ __launch_bounds__(256) void kan_main(
    const float* __restrict__ x,      // [B][D_IN]
    const float* __restrict__ bias,   // [D_OUT]
    float* __restrict__ out)          // [B][D_OUT]
{
    __shared__ float4 w_s[BPB][D_INF];
    __shared__ int    idx_s[BPB][D_INF];

    const int b0 = blockIdx.x * BPB;
    const float hf = (1.0f - 0.0f) / (float)(KNOTS - 1);

    // Phase 1: per-(b,i) Hermite weights (extrapolation folded in).
    for (int p = threadIdx.x; p < BPB * D_INF; p += blockDim.x) {
        int bl = p >> 7;
        int i  = p & (D_INF - 1);
        float xv = x[(b0 + bl) * D_INF + i];
        int idx;
        float wy0, wd0, wy1, wd1;
        if (xv < 0.0f) {                 // left linear extrapolation
            idx = 0;  wy0 = 1.f; wd0 = xv;        wy1 = 0.f; wd1 = 0.f;
        } else if (xv > 1.0f) {          // right linear extrapolation
            idx = KNOTS - 2; wy0 = 0.f; wd0 = 0.f; wy1 = 1.f; wd1 = xv - 1.0f;
        } else {
            idx = (int)floorf(xv / hf);
            if (idx > KNOTS - 2) idx = KNOTS - 2;
            float t  = (xv - (float)idx * hf) / hf;
            float t2 = t * t;
            float t3 = t2 * t;
            wy0 = 2.f * t3 - 3.f * t2 + 1.f;
            wd0 = (t3 - 2.f * t2 + t) * hf;
            wy1 = -2.f * t3 + 3.f * t2;
            wd1 = (t3 - t2) * hf;
        }
        w_s[bl][i]   = make_float4(wy0, wd0, wy1, wd1);
        idx_s[bl][i] = idx;
    }
    __syncthreads();

    const int warp = threadIdx.x >> 5;
    const int lane = threadIdx.x & 31;
    const int b    = b0 + warp;

    const float4* __restrict__ ct4 = reinterpret_cast<const float4*>(g_ct);
    const float4* __restrict__ dt4 = reinterpret_cast<const float4*>(g_dt);

    float4 acc = make_float4(0.f, 0.f, 0.f, 0.f);

    #pragma unroll 4
    for (int i = 0; i < D_INF; ++i) {
        int    idx = idx_s[warp][i];                 // warp-uniform
        float4 w   = w_s[warp][i];                   // warp-uniform broadcast
        int base = (i * KNOTS + idx) * (D_OUTF / 4) + lane;
        float4 v0 = __ldg(&ct4[base]);
        float4 s0 = __ldg(&dt4[base]);
        float4 v1 = __ldg(&ct4[base + (D_OUTF / 4)]);
        float4 s1 = __ldg(&dt4[base + (D_OUTF / 4)]);

        acc.x = fmaf(w.x, v0.x, acc.x);
        acc.y = fmaf(w.x, v0.y, acc.y);
        acc.z = fmaf(w.x, v0.z, acc.z);
        acc.w = fmaf(w.x, v0.w, acc.w);

        acc.x = fmaf(w.y, s0.x, acc.x);
        acc.y = fmaf(w.y, s0.y, acc.y);
        acc.z = fmaf(w.y, s0.z, acc.z);
        acc.w = fmaf(w.y, s0.w, acc.w);

        acc.x = fmaf(w.z, v1.x, acc.x);
        acc.y = fmaf(w.z, v1.y, acc.y);
        acc.z = fmaf(w.z, v1.z, acc.z);
        acc.w = fmaf(w.z, v1.w, acc.w);

        acc.x = fmaf(w.w, s1.x, acc.x);
        acc.y = fmaf(w.w, s1.y, acc.y);
        acc.z = fmaf(w.w, s1.z, acc.z);
        acc.w = fmaf(w.w, s1.w, acc.w);
    }

    float4 bb = __ldg(&reinterpret_cast<const float4*>(bias)[lane]);
    acc.x += bb.x; acc.y += bb.y; acc.z += bb.z; acc.w += bb.w;

    reinterpret_cast<float4*>(out)[b * (D_OUTF / 4) + lane] = acc;
}

// ---------------------------------------------------------------------------
// Launch
// ---------------------------------------------------------------------------
extern "C" void kernel_launch(void* const* d_in, const int* in_sizes, int n_in,
                              void* d_out, int out_size)
{
    const float* x      = (const float*)d_in[0];  // [4096,128]
    const float* coeffs = (const float*)d_in[1];  // [128,128,64]
    const float* bias   = (const float*)d_in[2];  // [128]
    const float* knots  = (const float*)d_in[3];  // [64]
    float* out = (float*)d_out;                   // [4096,128]

    kan_preprocess<<<D_INF, 128>>>(coeffs, knots);
    kan_main<<<NBATCH / BPB, 256>>>(x, bias, out);
}

// round 2
// speedup vs baseline: 1.0115x; 1.0115x over previous
#include <cuda_runtime.h>
#include <math.h>

#define D_INF   128
#define D_OUTF  128
#define KNOTS   64
#define NBATCH  4096
#define EPSF    1e-12f
#define BPB     4      // batches per block (2 warps per batch)

// Precomputed transposed tables: [i][k][o], contiguous in o.
__device__ float g_ct[D_INF * KNOTS * D_OUTF];
__device__ float g_dt[D_INF * KNOTS * D_OUTF];

// ---------------------------------------------------------------------------
// Kernel 1: transpose coeffs -> g_ct and compute PCHIP slopes -> g_dt.
// block = 128 threads (o), grid = 128 (i). Coeff reads staged through smem
// so global reads are k-contiguous (coalesced); writes coalesced over o.
// ---------------------------------------------------------------------------
__global__ __launch_bounds__(128) void kan_preprocess(
    const float* __restrict__ coeffs,   // [D_OUT][D_IN][K]
    const float* __restrict__ knots)    // [K]
{
    __shared__ float h_s[KNOTS - 1];
    __shared__ float ybuf[D_OUTF][KNOTS + 1];   // +1 pad: conflict-free col reads

    const int o = threadIdx.x;
    const int i = blockIdx.x;
    if (o < KNOTS - 1) h_s[o] = knots[o + 1] - knots[o];

    // Coalesced staging: flat index over (o,k); consecutive threads read
    // consecutive k within an o-row (coeffs contiguous in k).
    for (int j = 0; j < D_OUTF * KNOTS; j += 128) {
        int flat = j + threadIdx.x;
        int oo = flat >> 6;          // /KNOTS
        int kk = flat & (KNOTS - 1);
        ybuf[oo][kk] = coeffs[(oo * D_INF + i) * KNOTS + kk];
    }
    __syncthreads();

    const float* y = ybuf[o];
    float* ct = g_ct + i * (KNOTS * D_OUTF) + o;
    float* dt = g_dt + i * (KNOTS * D_OUTF) + o;

    float y0v = y[0];
    float y1v = y[1];
    ct[0]       = y0v;
    ct[D_OUTF]  = y1v;

    float delta_prev = (y1v - y0v) / (h_s[0] + EPSF);   // delta[0]
    const float delta0 = delta_prev;
    float delta1  = 0.f;
    float delta61 = 0.f;
    float prev_y  = y1v;

    #pragma unroll 1
    for (int k = 1; k <= KNOTS - 2; ++k) {
        float ynext = y[k + 1];
        ct[(k + 1) * D_OUTF] = ynext;
        float delta_cur = (ynext - prev_y) / (h_s[k] + EPSF);  // delta[k]
        if (k == 1)         delta1  = delta_cur;
        if (k == KNOTS - 3) delta61 = delta_cur;               // delta[K-3]
        float h0 = h_s[k - 1], h1 = h_s[k];
        float w1 = 2.f * h1 + h0;
        float w2 = h1 + 2.f * h0;
        float dd = 0.f;
        if (delta_prev * delta_cur > 0.f) {
            float denom = w1 / (delta_prev + EPSF) + w2 / (delta_cur + EPSF);
            dd = (w1 + w2) / (denom + EPSF);
        }
        dt[k * D_OUTF] = dd;
        delta_prev = delta_cur;
        prev_y = ynext;
    }
    const float delta62 = delta_prev;  // delta[K-2]

    float df = ((2.f * h_s[0] + h_s[1]) * delta0 - h_s[0] * delta1) /
               (h_s[0] + h_s[1] + EPSF);
    df = (df * delta0 <= 0.f) ? 0.f : df;
    df = (fabsf(df) > 3.f * fabsf(delta0)) ? 3.f * delta0 : df;
    dt[0] = df;

    float dl = ((2.f * h_s[KNOTS - 2] + h_s[KNOTS - 3]) * delta62 -
                h_s[KNOTS - 2] * delta61) /
               (h_s[KNOTS - 2] + h_s[KNOTS - 3] + EPSF);
    dl = (dl * delta62 <= 0.f) ? 0.f : dl;
    dl = (fabsf(dl) > 3.f * fabsf(delta62)) ? 3.f * delta62 : dl;
    dt[(KNOTS - 1) * D_OUTF] = dl;
}

// ---------------------------------------------------------------------------
// Kernel 2: main evaluation.
// block = 256 threads = 8 warps; 4 batches/block, 2 warps per batch (i-halves).
// lane <-> o-quad (float4). Right extrapolation remapped to idx=63 with
// weights (1, x-1, 0, 0) so the FIRST load pair is unconditional; the second
// pair is only loaded for interior points (~34%) -> ~33% less gather traffic.
// All branches are warp-uniform (idx/weights identical across lanes).
// ---------------------------------------------------------------------------
__global__ __launch_bounds__(256) void kan_main(
    const float* __restrict__ x,      // [B][D_IN]
    const float* __restrict__ bias,   // [D_OUT]
    float* __restrict__ out)          // [B][D_OUT]
{
    __shared__ float4 w_s[BPB][D_INF];
    __shared__ int    idx_s[BPB][D_INF];
    __shared__ float4 part[BPB][32];

    const int b0 = blockIdx.x * BPB;
    const float hf = 1.0f / (float)(KNOTS - 1);

    // Phase 1: per-(b,i) Hermite weights (extrapolation folded in).
    for (int p = threadIdx.x; p < BPB * D_INF; p += blockDim.x) {
        int bl = p >> 7;
        int i  = p & (D_INF - 1);
        float xv = x[(b0 + bl) * D_INF + i];
        int idx;
        float wy0, wd0, wy1, wd1;
        if (xv < 0.0f) {                 // left linear: ct[0] + dt[0]*x
            idx = 0;  wy0 = 1.f; wd0 = xv;        wy1 = 0.f; wd1 = 0.f;
        } else if (xv > 1.0f) {          // right linear: ct[63] + dt[63]*(x-1)
            idx = KNOTS - 1; wy0 = 1.f; wd0 = xv - 1.0f; wy1 = 0.f; wd1 = 0.f;
        } else {
            idx = (int)floorf(xv * (float)(KNOTS - 1));
            if (idx > KNOTS - 2) idx = KNOTS - 2;
            float t  = (xv - (float)idx * hf) * (float)(KNOTS - 1);
            float t2 = t * t;
            float t3 = t2 * t;
            wy0 = 2.f * t3 - 3.f * t2 + 1.f;
            wd0 = (t3 - 2.f * t2 + t) * hf;
            wy1 = -2.f * t3 + 3.f * t2;
            wd1 = (t3 - t2) * hf;
        }
        w_s[bl][i]   = make_float4(wy0, wd0, wy1, wd1);
        idx_s[bl][i] = idx;
    }
    __syncthreads();

    const int warp = threadIdx.x >> 5;
    const int lane = threadIdx.x & 31;
    const int bl   = warp >> 1;            // batch within block
    const int i0   = (warp & 1) * (D_INF / 2);

    const float4* __restrict__ ct4 = reinterpret_cast<const float4*>(g_ct);
    const float4* __restrict__ dt4 = reinterpret_cast<const float4*>(g_dt);

    float4 acc = make_float4(0.f, 0.f, 0.f, 0.f);

    #pragma unroll 4
    for (int j = 0; j < D_INF / 2; ++j) {
        int    i   = i0 + j;
        int    idx = idx_s[bl][i];                   // warp-uniform
        float4 w   = w_s[bl][i];                     // warp-uniform broadcast
        int base = (i * KNOTS + idx) * (D_OUTF / 4) + lane;

        float4 v0 = __ldg(&ct4[base]);               // always needed
        float4 s0 = __ldg(&dt4[base]);

        acc.x = fmaf(w.x, v0.x, acc.x);
        acc.y = fmaf(w.x, v0.y, acc.y);
        acc.z = fmaf(w.x, v0.z, acc.z);
        acc.w = fmaf(w.x, v0.w, acc.w);
        acc.x = fmaf(w.y, s0.x, acc.x);
        acc.y = fmaf(w.y, s0.y, acc.y);
        acc.z = fmaf(w.y, s0.z, acc.z);
        acc.w = fmaf(w.y, s0.w, acc.w);

        if (w.z != 0.f || w.w != 0.f) {               // interior only (uniform)
            float4 v1 = __ldg(&ct4[base + (D_OUTF / 4)]);
            float4 s1 = __ldg(&dt4[base + (D_OUTF / 4)]);
            acc.x = fmaf(w.z, v1.x, acc.x);
            acc.y = fmaf(w.z, v1.y, acc.y);
            acc.z = fmaf(w.z, v1.z, acc.z);
            acc.w = fmaf(w.z, v1.w, acc.w);
            acc.x = fmaf(w.w, s1.x, acc.x);
            acc.y = fmaf(w.w, s1.y, acc.y);
            acc.z = fmaf(w.w, s1.z, acc.z);
            acc.w = fmaf(w.w, s1.w, acc.w);
        }
    }

    // Combine the two i-halves of each batch.
    if (warp & 1) {
        part[bl][lane] = acc;
    }
    __syncthreads();
    if (!(warp & 1)) {
        float4 pv = part[bl][lane];
        float4 bb = __ldg(&reinterpret_cast<const float4*>(bias)[lane]);
        acc.x += pv.x + bb.x;
        acc.y += pv.y + bb.y;
        acc.z += pv.z + bb.z;
        acc.w += pv.w + bb.w;
        reinterpret_cast<float4*>(out)[(b0 + bl) * (D_OUTF / 4) + lane] = acc;
    }
}

// ---------------------------------------------------------------------------
// Launch
// ---------------------------------------------------------------------------
extern "C" void kernel_launch(void* const* d_in, const int* in_sizes, int n_in,
                              void* d_out, int out_size)
{
    const float* x      = (const float*)d_in[0];  // [4096,128]
    const float* coeffs = (const float*)d_in[1];  // [128,128,64]
    const float* bias   = (const float*)d_in[2];  // [128]
    const float* knots  = (const float*)d_in[3];  // [64]
    float* out = (float*)d_out;                   // [4096,128]

    kan_preprocess<<<D_INF, 128>>>(coeffs, knots);
    kan_main<<<NBATCH / BPB, 256>>>(x, bias, out);
}

// round 6
// speedup vs baseline: 1.3538x; 1.3384x over previous
#include <cuda_runtime.h>
#include <math.h>

#define D_INF   128
#define D_OUTF  128
#define KNOTS   64
#define NBATCH  4096
#define EPSF    1e-12f
#define BPB     4      // batches per block (2 warps per batch, i-halves)
#define FULLMASK 0xffffffffu

// Interleaved table: [i][k][ ct(128) | dt(128) ]  (1KB per (i,k) row-pair)
__device__ float g_t[D_INF * KNOTS * 2 * D_OUTF];

// ---------------------------------------------------------------------------
// packed f32x2 helpers (FFMA2 — only reachable via PTX)
// ---------------------------------------------------------------------------
__device__ __forceinline__ void fma2(unsigned long long& acc,
                                     unsigned long long v,
                                     unsigned long long w) {
    asm("fma.rn.f32x2 %0, %1, %2, %3;" : "=l"(acc) : "l"(v), "l"(w), "l"(acc));
}
__device__ __forceinline__ unsigned long long pk2(float a) {
    unsigned long long r;
    asm("mov.b64 %0, {%1, %1};" : "=l"(r) : "f"(a));
    return r;
}
__device__ __forceinline__ float2 unpk(unsigned long long v) {
    float2 r;
    asm("mov.b64 {%0, %1}, %2;" : "=f"(r.x), "=f"(r.y) : "l"(v));
    return r;
}

// ---------------------------------------------------------------------------
// Kernel 1: PCHIP slopes + transpose into interleaved table.
// block = 128 threads (o), grid = 128 (i). Coalesced reads via smem staging.
// ---------------------------------------------------------------------------
__global__ __launch_bounds__(128) void kan_preprocess(
    const float* __restrict__ coeffs,   // [D_OUT][D_IN][K]
    const float* __restrict__ knots)    // [K]
{
    __shared__ float h_s[KNOTS - 1];
    __shared__ float ybuf[D_OUTF][KNOTS + 1];

    const int o = threadIdx.x;
    const int i = blockIdx.x;
    if (o < KNOTS - 1) h_s[o] = knots[o + 1] - knots[o];

    for (int j = 0; j < D_OUTF * KNOTS; j += 128) {
        int flat = j + threadIdx.x;
        int oo = flat >> 6;
        int kk = flat & (KNOTS - 1);
        ybuf[oo][kk] = coeffs[(oo * D_INF + i) * KNOTS + kk];
    }
    __syncthreads();

    const float* y = ybuf[o];
    float* ct = g_t + (i * KNOTS) * (2 * D_OUTF) + o;            // +k*256
    float* dt = g_t + (i * KNOTS) * (2 * D_OUTF) + D_OUTF + o;   // +k*256

    float y0v = y[0];
    float y1v = y[1];
    ct[0]           = y0v;
    ct[2 * D_OUTF]  = y1v;

    float delta_prev = (y1v - y0v) / (h_s[0] + EPSF);
    const float delta0 = delta_prev;
    float delta1  = 0.f;
    float delta61 = 0.f;
    float prev_y  = y1v;

    #pragma unroll 1
    for (int k = 1; k <= KNOTS - 2; ++k) {
        float ynext = y[k + 1];
        ct[(k + 1) * 2 * D_OUTF] = ynext;
        float delta_cur = (ynext - prev_y) / (h_s[k] + EPSF);
        if (k == 1)         delta1  = delta_cur;
        if (k == KNOTS - 3) delta61 = delta_cur;
        float h0 = h_s[k - 1], h1 = h_s[k];
        float w1 = 2.f * h1 + h0;
        float w2 = h1 + 2.f * h0;
        float dd = 0.f;
        if (delta_prev * delta_cur > 0.f) {
            float denom = w1 / (delta_prev + EPSF) + w2 / (delta_cur + EPSF);
            dd = (w1 + w2) / (denom + EPSF);
        }
        dt[k * 2 * D_OUTF] = dd;
        delta_prev = delta_cur;
        prev_y = ynext;
    }
    const float delta62 = delta_prev;

    float df = ((2.f * h_s[0] + h_s[1]) * delta0 - h_s[0] * delta1) /
               (h_s[0] + h_s[1] + EPSF);
    df = (df * delta0 <= 0.f) ? 0.f : df;
    df = (fabsf(df) > 3.f * fabsf(delta0)) ? 3.f * delta0 : df;
    dt[0] = df;

    float dl = ((2.f * h_s[KNOTS - 2] + h_s[KNOTS - 3]) * delta62 -
                h_s[KNOTS - 2] * delta61) /
               (h_s[KNOTS - 2] + h_s[KNOTS - 3] + EPSF);
    dl = (dl * delta62 <= 0.f) ? 0.f : dl;
    dl = (fabsf(dl) > 3.f * fabsf(delta62)) ? 3.f * delta62 : dl;
    dt[(KNOTS - 1) * 2 * D_OUTF] = dl;
}

// ---------------------------------------------------------------------------
// Kernel 2: main evaluation.
// Phase 1 compacts each (batch, i-half) into extrapolation / interior lists
// (warp-ballot + 1 atomic pair per warp). Phase 2 runs two branch-free loops:
//   extrap:  2x LDG.128 + 4 FFMA2   (~66% of i's)
//   interior:4x LDG.128 + 8 FFMA2   (~34%)
// warp <-> (batch, i-half), lane <-> o-quad.
// ---------------------------------------------------------------------------
__global__ __launch_bounds__(256) void kan_main(
    const float* __restrict__ x,      // [B][D_IN]
    const float* __restrict__ bias,   // [D_OUT]
    float* __restrict__ out)          // [B][D_OUT]
{
    __shared__ int    eb[BPB][2][64];     // ext row base (ulonglong2 units)
    __shared__ float2 ew[BPB][2][64];     // ext weights (wy, wd)
    __shared__ int    ib[BPB][2][64];     // interior row base
    __shared__ float4 iw[BPB][2][64];     // interior weights
    __shared__ int    cnt[BPB][2][2];     // [bl][half][ext|int]
    __shared__ float4 part[BPB][32];

    const int tid  = threadIdx.x;
    const int lane = tid & 31;
    const int b0   = blockIdx.x * BPB;
    const float hf = 1.0f / (float)(KNOTS - 1);

    if (tid < BPB * 2 * 2) ((int*)cnt)[tid] = 0;
    __syncthreads();

    // -------- Phase 1: classify + compact ---------------------------------
    for (int p = tid; p < BPB * D_INF; p += 256) {
        int bl   = p >> 7;
        int i    = p & (D_INF - 1);
        int half = i >> 6;
        float xv = x[(b0 + bl) * D_INF + i];

        bool ext = (xv < 0.0f) | (xv > 1.0f);
        int idx;
        float2 we;
        float4 wi;
        if (xv < 0.0f) {
            idx = 0;          we = make_float2(1.f, xv);
        } else if (xv > 1.0f) {
            idx = KNOTS - 1;  we = make_float2(1.f, xv - 1.0f);
        } else {
            idx = (int)floorf(xv * (float)(KNOTS - 1));
            if (idx > KNOTS - 2) idx = KNOTS - 2;
            float t  = (xv - (float)idx * hf) * (float)(KNOTS - 1);
            float t2 = t * t;
            float t3 = t2 * t;
            wi = make_float4(2.f * t3 - 3.f * t2 + 1.f,
                             (t3 - 2.f * t2 + t) * hf,
                             -2.f * t3 + 3.f * t2,
                             (t3 - t2) * hf);
        }

        unsigned m  = __ballot_sync(FULLMASK, ext);
        int nE = __popc(m);
        int baseE = 0, baseI = 0;
        if (lane == 0) {
            baseE = atomicAdd(&cnt[bl][half][0], nE);
            baseI = atomicAdd(&cnt[bl][half][1], 32 - nE);
        }
        baseE = __shfl_sync(FULLMASK, baseE, 0);
        baseI = __shfl_sync(FULLMASK, baseI, 0);
        unsigned ltm = (1u << lane) - 1u;
        int rankE = __popc(m & ltm);
        int rankI = lane - rankE;
        int rowbase = ((i << 6) + idx) << 6;   // (i*64+idx) * 64 ull2-units

        if (ext) {
            int s = baseE + rankE;
            eb[bl][half][s] = rowbase;
            ew[bl][half][s] = we;
        } else {
            int s = baseI + rankI;
            ib[bl][half][s] = rowbase;
            iw[bl][half][s] = wi;
        }
    }
    __syncthreads();

    // -------- Phase 2: gather + accumulate --------------------------------
    const int warp = tid >> 5;
    const int bl   = warp >> 1;
    const int half = warp & 1;
    const int nE = cnt[bl][half][0];
    const int nI = cnt[bl][half][1];

    const ulonglong2* __restrict__ T = reinterpret_cast<const ulonglong2*>(g_t);

    unsigned long long a0 = 0ull, a1 = 0ull;   // acc: o-quad as 2x f32x2

    #pragma unroll 2
    for (int j = 0; j < nE; ++j) {
        int rb = eb[bl][half][j] + lane;
        ulonglong2 v = T[rb];           // ct quad
        ulonglong2 s = T[rb + 32];      // dt quad
        float2 w = ew[bl][half][j];
        unsigned long long wv = pk2(w.x);
        unsigned long long wd = pk2(w.y);
        fma2(a0, v.x, wv); fma2(a1, v.y, wv);
        fma2(a0, s.x, wd); fma2(a1, s.y, wd);
    }

    #pragma unroll 2
    for (int j = 0; j < nI; ++j) {
        int rb = ib[bl][half][j] + lane;
        ulonglong2 v0 = T[rb];
        ulonglong2 s0 = T[rb + 32];
        ulonglong2 v1 = T[rb + 64];
        ulonglong2 s1 = T[rb + 96];
        float4 w = iw[bl][half][j];
        unsigned long long w0 = pk2(w.x);
        unsigned long long w1 = pk2(w.y);
        unsigned long long w2 = pk2(w.z);
        unsigned long long w3 = pk2(w.w);
        fma2(a0, v0.x, w0); fma2(a1, v0.y, w0);
        fma2(a0, s0.x, w1); fma2(a1, s0.y, w1);
        fma2(a0, v1.x, w2); fma2(a1, v1.y, w2);
        fma2(a0, s1.x, w3); fma2(a1, s1.y, w3);
    }

    float2 lo = unpk(a0);
    float2 hi = unpk(a1);
    float4 acc = make_float4(lo.x, lo.y, hi.x, hi.y);

    // Combine i-halves; add bias; write.
    if (half) {
        part[bl][lane] = acc;
    }
    __syncthreads();
    if (!half) {
        float4 pv = part[bl][lane];
        float4 bb = __ldg(&reinterpret_cast<const float4*>(bias)[lane]);
        acc.x += pv.x + bb.x;
        acc.y += pv.y + bb.y;
        acc.z += pv.z + bb.z;
        acc.w += pv.w + bb.w;
        reinterpret_cast<float4*>(out)[(b0 + bl) * (D_OUTF / 4) + lane] = acc;
    }
}

// ---------------------------------------------------------------------------
// Launch
// ---------------------------------------------------------------------------
extern "C" void kernel_launch(void* const* d_in, const int* in_sizes, int n_in,
                              void* d_out, int out_size)
{
    const float* x      = (const float*)d_in[0];  // [4096,128]
    const float* coeffs = (const float*)d_in[1];  // [128,128,64]
    const float* bias   = (const float*)d_in[2];  // [128]
    const float* knots  = (const float*)d_in[3];  // [64]
    float* out = (float*)d_out;                   // [4096,128]

    kan_preprocess<<<D_INF, 128>>>(coeffs, knots);
    kan_main<<<NBATCH / BPB, 256>>>(x, bias, out);
}

// round 9
// speedup vs baseline: 1.6527x; 1.2208x over previous
#include <cuda_runtime.h>
#include <math.h>

#define D_INF   128
#define D_OUTF  128
#define KNOTS   64
#define NBATCH  4096
#define EPSF    1e-12f
#define BPB     4      // batches per block (2 warps per batch, i-halves)
#define FULLMASK 0xffffffffu

// Interleaved table: [i][k][ ct(128) | dt(128) ]  (1KB per (i,k) row-pair)
__device__ float g_t[D_INF * KNOTS * 2 * D_OUTF];

// ---------------------------------------------------------------------------
// packed f32x2 helpers (FFMA2 — only reachable via PTX)
// ---------------------------------------------------------------------------
__device__ __forceinline__ void fma2(unsigned long long& acc,
                                     unsigned long long v,
                                     unsigned long long w) {
    asm("fma.rn.f32x2 %0, %1, %2, %3;" : "=l"(acc) : "l"(v), "l"(w), "l"(acc));
}
__device__ __forceinline__ unsigned long long pk2(float a) {
    unsigned long long r;
    asm("mov.b64 %0, {%1, %1};" : "=l"(r) : "f"(a));
    return r;
}
__device__ __forceinline__ float2 unpk(unsigned long long v) {
    float2 r;
    asm("mov.b64 {%0, %1}, %2;" : "=f"(r.x), "=f"(r.y) : "l"(v));
    return r;
}

// ---------------------------------------------------------------------------
// Kernel 1: PCHIP slopes + transpose into interleaved table.
// grid = 128 (i), block = 512 = (o:128, q:4); each thread owns 16 k's.
// Deltas are data-parallel (no serial chain); interior slope uses ONE
// __fdividef via the algebraic rewrite
//   (w1+w2)/(w1/dp + w2/dc + EPS) == (w1+w2)*dp*dc/(w1*dc + w2*dp + EPS*dp*dc)
// ---------------------------------------------------------------------------
__global__ __launch_bounds__(512) void kan_preprocess(
    const float* __restrict__ coeffs,   // [D_OUT][D_IN][K]
    const float* __restrict__ knots)    // [K]
{
    __shared__ float ybuf[D_OUTF][KNOTS + 1];   // +1 pad
    __shared__ float h_s[KNOTS];                // h[0..62]
    __shared__ float rh_s[KNOTS];               // 1/(h+EPS)

    const int tid = threadIdx.x;
    const int i   = blockIdx.x;
    const int o   = tid & 127;
    const int q   = tid >> 7;

    if (tid < KNOTS - 1) {
        float h = knots[tid + 1] - knots[tid];
        h_s[tid]  = h;
        rh_s[tid] = 1.0f / (h + EPSF);
    }
    // Coalesced staging (k contiguous in gmem).
    for (int j = tid; j < D_OUTF * KNOTS; j += 512) {
        int oo = j >> 6;
        int kk = j & (KNOTS - 1);
        ybuf[oo][kk] = coeffs[(oo * D_INF + i) * KNOTS + kk];
    }
    __syncthreads();

    const float* y = ybuf[o];
    float* ct = g_t + (i * KNOTS) * (2 * D_OUTF) + o;
    float* dt = ct + D_OUTF;
    const int k0 = q * 16;

    // ct writes (transpose) — coalesced over o.
    #pragma unroll
    for (int kk = 0; kk < 16; ++kk) {
        int k = k0 + kk;
        ct[k * 2 * D_OUTF] = y[k];
    }

    // deltas del[kk] = delta[k0-1+kk], kk = 0..16
    float del[17];
    #pragma unroll
    for (int kk = 0; kk < 17; ++kk) {
        int k = k0 - 1 + kk;
        del[kk] = (k >= 0 && k < KNOTS - 1) ? (y[k + 1] - y[k]) * rh_s[k] : 0.f;
    }

    // interior slopes
    #pragma unroll
    for (int kk = 0; kk < 16; ++kk) {
        int k = k0 + kk;
        if (k >= 1 && k <= KNOTS - 2) {
            float dprev = del[kk];
            float dcur  = del[kk + 1];
            float h0 = h_s[k - 1], h1 = h_s[k];
            float w1 = 2.f * h1 + h0;
            float w2 = h1 + 2.f * h0;
            float dpe = dprev + EPSF;
            float dce = dcur + EPSF;
            float num = (w1 + w2) * dpe * dce;
            float den = w1 * dce + w2 * dpe + EPSF * dpe * dce;
            float dd  = (dprev * dcur > 0.f) ? __fdividef(num, den) : 0.f;
            dt[k * 2 * D_OUTF] = dd;
        }
    }

    // endpoints (q==0 owns k=0; q==3 owns k=63) — warp-uniform branches
    if (k0 == 0) {
        float delta0 = del[1];                       // delta[0]
        float delta1 = del[2];                       // delta[1]
        float df = __fdividef((2.f * h_s[0] + h_s[1]) * delta0 - h_s[0] * delta1,
                              h_s[0] + h_s[1] + EPSF);
        df = (df * delta0 <= 0.f) ? 0.f : df;
        df = (fabsf(df) > 3.f * fabsf(delta0)) ? 3.f * delta0 : df;
        dt[0] = df;
    }
    if (k0 == 48) {
        float delta62 = del[15];                     // delta[62]
        float delta61 = del[14];                     // delta[61]
        float dl = __fdividef((2.f * h_s[KNOTS - 2] + h_s[KNOTS - 3]) * delta62 -
                              h_s[KNOTS - 2] * delta61,
                              h_s[KNOTS - 2] + h_s[KNOTS - 3] + EPSF);
        dl = (dl * delta62 <= 0.f) ? 0.f : dl;
        dl = (fabsf(dl) > 3.f * fabsf(delta62)) ? 3.f * delta62 : dl;
        dt[(KNOTS - 1) * 2 * D_OUTF] = dl;
    }
}

// ---------------------------------------------------------------------------
// Kernel 2: main evaluation (unchanged structure from R6; ext loop unroll 4).
// ---------------------------------------------------------------------------
__global__ __launch_bounds__(256) void kan_main(
    const float* __restrict__ x,      // [B][D_IN]
    const float* __restrict__ bias,   // [D_OUT]
    float* __restrict__ out)          // [B][D_OUT]
{
    __shared__ int    eb[BPB][2][64];     // ext row base (ulonglong2 units)
    __shared__ float2 ew[BPB][2][64];     // ext weights (wy, wd)
    __shared__ int    ib[BPB][2][64];     // interior row base
    __shared__ float4 iw[BPB][2][64];     // interior weights
    __shared__ int    cnt[BPB][2][2];     // [bl][half][ext|int]
    __shared__ float4 part[BPB][32];

    const int tid  = threadIdx.x;
    const int lane = tid & 31;
    const int b0   = blockIdx.x * BPB;
    const float hf = 1.0f / (float)(KNOTS - 1);

    if (tid < BPB * 2 * 2) ((int*)cnt)[tid] = 0;
    __syncthreads();

    // -------- Phase 1: classify + compact ---------------------------------
    for (int p = tid; p < BPB * D_INF; p += 256) {
        int bl   = p >> 7;
        int i    = p & (D_INF - 1);
        int half = i >> 6;
        float xv = x[(b0 + bl) * D_INF + i];

        bool ext = (xv < 0.0f) | (xv > 1.0f);
        int idx;
        float2 we;
        float4 wi;
        if (xv < 0.0f) {
            idx = 0;          we = make_float2(1.f, xv);
        } else if (xv > 1.0f) {
            idx = KNOTS - 1;  we = make_float2(1.f, xv - 1.0f);
        } else {
            idx = (int)floorf(xv * (float)(KNOTS - 1));
            if (idx > KNOTS - 2) idx = KNOTS - 2;
            float t  = (xv - (float)idx * hf) * (float)(KNOTS - 1);
            float t2 = t * t;
            float t3 = t2 * t;
            wi = make_float4(2.f * t3 - 3.f * t2 + 1.f,
                             (t3 - 2.f * t2 + t) * hf,
                             -2.f * t3 + 3.f * t2,
                             (t3 - t2) * hf);
        }

        unsigned m  = __ballot_sync(FULLMASK, ext);
        int nE = __popc(m);
        int baseE = 0, baseI = 0;
        if (lane == 0) {
            baseE = atomicAdd(&cnt[bl][half][0], nE);
            baseI = atomicAdd(&cnt[bl][half][1], 32 - nE);
        }
        baseE = __shfl_sync(FULLMASK, baseE, 0);
        baseI = __shfl_sync(FULLMASK, baseI, 0);
        unsigned ltm = (1u << lane) - 1u;
        int rankE = __popc(m & ltm);
        int rankI = lane - rankE;
        int rowbase = ((i << 6) + idx) << 6;   // (i*64+idx) * 64 ull2-units

        if (ext) {
            int s = baseE + rankE;
            eb[bl][half][s] = rowbase;
            ew[bl][half][s] = we;
        } else {
            int s = baseI + rankI;
            ib[bl][half][s] = rowbase;
            iw[bl][half][s] = wi;
        }
    }
    __syncthreads();

    // -------- Phase 2: gather + accumulate --------------------------------
    const int warp = tid >> 5;
    const int bl   = warp >> 1;
    const int half = warp & 1;
    const int nE = cnt[bl][half][0];
    const int nI = cnt[bl][half][1];

    const ulonglong2* __restrict__ T = reinterpret_cast<const ulonglong2*>(g_t);

    unsigned long long a0 = 0ull, a1 = 0ull;   // acc: o-quad as 2x f32x2

    #pragma unroll 4
    for (int j = 0; j < nE; ++j) {
        int rb = eb[bl][half][j] + lane;
        ulonglong2 v = T[rb];           // ct quad
        ulonglong2 s = T[rb + 32];      // dt quad
        float2 w = ew[bl][half][j];
        unsigned long long wv = pk2(w.x);
        unsigned long long wd = pk2(w.y);
        fma2(a0, v.x, wv); fma2(a1, v.y, wv);
        fma2(a0, s.x, wd); fma2(a1, s.y, wd);
    }

    #pragma unroll 2
    for (int j = 0; j < nI; ++j) {
        int rb = ib[bl][half][j] + lane;
        ulonglong2 v0 = T[rb];
        ulonglong2 s0 = T[rb + 32];
        ulonglong2 v1 = T[rb + 64];
        ulonglong2 s1 = T[rb + 96];
        float4 w = iw[bl][half][j];
        unsigned long long w0 = pk2(w.x);
        unsigned long long w1 = pk2(w.y);
        unsigned long long w2 = pk2(w.z);
        unsigned long long w3 = pk2(w.w);
        fma2(a0, v0.x, w0); fma2(a1, v0.y, w0);
        fma2(a0, s0.x, w1); fma2(a1, s0.y, w1);
        fma2(a0, v1.x, w2); fma2(a1, v1.y, w2);
        fma2(a0, s1.x, w3); fma2(a1, s1.y, w3);
    }

    float2 lo = unpk(a0);
    float2 hi = unpk(a1);
    float4 acc = make_float4(lo.x, lo.y, hi.x, hi.y);

    // Combine i-halves; add bias; write.
    if (half) {
        part[bl][lane] = acc;
    }
    __syncthreads();
    if (!half) {
        float4 pv = part[bl][lane];
        float4 bb = __ldg(&reinterpret_cast<const float4*>(bias)[lane]);
        acc.x += pv.x + bb.x;
        acc.y += pv.y + bb.y;
        acc.z += pv.z + bb.z;
        acc.w += pv.w + bb.w;
        reinterpret_cast<float4*>(out)[(b0 + bl) * (D_OUTF / 4) + lane] = acc;
    }
}

// ---------------------------------------------------------------------------
// Launch
// ---------------------------------------------------------------------------
extern "C" void kernel_launch(void* const* d_in, const int* in_sizes, int n_in,
                              void* d_out, int out_size)
{
    const float* x      = (const float*)d_in[0];  // [4096,128]
    const float* coeffs = (const float*)d_in[1];  // [128,128,64]
    const float* bias   = (const float*)d_in[2];  // [128]
    const float* knots  = (const float*)d_in[3];  // [64]
    float* out = (float*)d_out;                   // [4096,128]

    kan_preprocess<<<D_INF, 512>>>(coeffs, knots);
    kan_main<<<NBATCH / BPB, 256>>>(x, bias, out);
}

// round 10
// speedup vs baseline: 2.0257x; 1.2257x over previous
#include <cuda_runtime.h>
#include <cuda_fp16.h>
#include <math.h>

#define D_INF   128
#define D_OUTF  128
#define KNOTS   64
#define NBATCH  4096
#define EPSF    1e-12f
#define BPB     4      // batches per block (2 warps per batch, i-halves)
#define FULLMASK 0xffffffffu

// Interleaved fp16 table: [i][k][ ct(128) | dt(128) ]  (512B per (i,k) pair)
__device__ __half g_th[D_INF * KNOTS * 2 * D_OUTF];

// ---------------------------------------------------------------------------
// quad fp16 load-convert-fma: v holds 4 halfs (one o-quad)
// ---------------------------------------------------------------------------
__device__ __forceinline__ void qfma(float4& a, uint2 v, float w) {
    float2 p0 = __half22float2(*reinterpret_cast<const __half2*>(&v.x));
    float2 p1 = __half22float2(*reinterpret_cast<const __half2*>(&v.y));
    a.x = fmaf(w, p0.x, a.x);
    a.y = fmaf(w, p0.y, a.y);
    a.z = fmaf(w, p1.x, a.z);
    a.w = fmaf(w, p1.y, a.w);
}

// ---------------------------------------------------------------------------
// Kernel 1: PCHIP slopes + transpose into interleaved fp16 table.
// grid = 128 (i), block = 512 = (o:128, q:4); each thread owns 16 k's.
// All math in fp32; only the final store quantizes to fp16.
// ---------------------------------------------------------------------------
__global__ __launch_bounds__(512) void kan_preprocess(
    const float* __restrict__ coeffs,   // [D_OUT][D_IN][K]
    const float* __restrict__ knots)    // [K]
{
    __shared__ float ybuf[D_OUTF][KNOTS + 1];   // +1 pad
    __shared__ float h_s[KNOTS];
    __shared__ float rh_s[KNOTS];

    const int tid = threadIdx.x;
    const int i   = blockIdx.x;
    const int o   = tid & 127;
    const int q   = tid >> 7;

    if (tid < KNOTS - 1) {
        float h = knots[tid + 1] - knots[tid];
        h_s[tid]  = h;
        rh_s[tid] = 1.0f / (h + EPSF);
    }
    for (int j = tid; j < D_OUTF * KNOTS; j += 512) {
        int oo = j >> 6;
        int kk = j & (KNOTS - 1);
        ybuf[oo][kk] = coeffs[(oo * D_INF + i) * KNOTS + kk];
    }
    __syncthreads();

    const float* y = ybuf[o];
    __half* ct = g_th + (i * KNOTS) * (2 * D_OUTF) + o;
    __half* dt = ct + D_OUTF;
    const int k0 = q * 16;

    #pragma unroll
    for (int kk = 0; kk < 16; ++kk) {
        int k = k0 + kk;
        ct[k * 2 * D_OUTF] = __float2half(y[k]);
    }

    // deltas del[kk] = delta[k0-1+kk], kk = 0..16
    float del[17];
    #pragma unroll
    for (int kk = 0; kk < 17; ++kk) {
        int k = k0 - 1 + kk;
        del[kk] = (k >= 0 && k < KNOTS - 1) ? (y[k + 1] - y[k]) * rh_s[k] : 0.f;
    }

    #pragma unroll
    for (int kk = 0; kk < 16; ++kk) {
        int k = k0 + kk;
        if (k >= 1 && k <= KNOTS - 2) {
            float dprev = del[kk];
            float dcur  = del[kk + 1];
            float h0 = h_s[k - 1], h1 = h_s[k];
            float w1 = 2.f * h1 + h0;
            float w2 = h1 + 2.f * h0;
            float dpe = dprev + EPSF;
            float dce = dcur + EPSF;
            float num = (w1 + w2) * dpe * dce;
            float den = w1 * dce + w2 * dpe + EPSF * dpe * dce;
            float dd  = (dprev * dcur > 0.f) ? __fdividef(num, den) : 0.f;
            dt[k * 2 * D_OUTF] = __float2half(dd);
        }
    }

    if (k0 == 0) {
        float delta0 = del[1];
        float delta1 = del[2];
        float df = __fdividef((2.f * h_s[0] + h_s[1]) * delta0 - h_s[0] * delta1,
                              h_s[0] + h_s[1] + EPSF);
        df = (df * delta0 <= 0.f) ? 0.f : df;
        df = (fabsf(df) > 3.f * fabsf(delta0)) ? 3.f * delta0 : df;
        dt[0] = __float2half(df);
    }
    if (k0 == 48) {
        float delta62 = del[15];
        float delta61 = del[14];
        float dl = __fdividef((2.f * h_s[KNOTS - 2] + h_s[KNOTS - 3]) * delta62 -
                              h_s[KNOTS - 2] * delta61,
                              h_s[KNOTS - 2] + h_s[KNOTS - 3] + EPSF);
        dl = (dl * delta62 <= 0.f) ? 0.f : dl;
        dl = (fabsf(dl) > 3.f * fabsf(delta62)) ? 3.f * delta62 : dl;
        dt[(KNOTS - 1) * 2 * D_OUTF] = __float2half(dl);
    }
}

// ---------------------------------------------------------------------------
// Kernel 2: main evaluation. Same compaction structure as R6/R9, but the
// table is fp16: rows are 256B, gathers are LDG.64 per lane (2 wf per row),
// halving L1 wavefront traffic. Weights stay fp32; convert-then-FFMA.
// Row-pair (i,k) = 64 uint2 units: ct = [0,32), dt = [32,64).
// ---------------------------------------------------------------------------
__global__ __launch_bounds__(256) void kan_main(
    const float* __restrict__ x,      // [B][D_IN]
    const float* __restrict__ bias,   // [D_OUT]
    float* __restrict__ out)          // [B][D_OUT]
{
    __shared__ int    eb[BPB][2][64];     // ext row base (uint2 units)
    __shared__ float2 ew[BPB][2][64];     // ext weights (wy, wd)
    __shared__ int    ib[BPB][2][64];     // interior row base
    __shared__ float4 iw[BPB][2][64];     // interior weights
    __shared__ int    cnt[BPB][2][2];     // [bl][half][ext|int]
    __shared__ float4 part[BPB][32];

    const int tid  = threadIdx.x;
    const int lane = tid & 31;
    const int b0   = blockIdx.x * BPB;
    const float hf = 1.0f / (float)(KNOTS - 1);

    if (tid < BPB * 2 * 2) ((int*)cnt)[tid] = 0;
    __syncthreads();

    // -------- Phase 1: classify + compact ---------------------------------
    for (int p = tid; p < BPB * D_INF; p += 256) {
        int bl   = p >> 7;
        int i    = p & (D_INF - 1);
        int half = i >> 6;
        float xv = x[(b0 + bl) * D_INF + i];

        bool ext = (xv < 0.0f) | (xv > 1.0f);
        int idx;
        float2 we;
        float4 wi;
        if (xv < 0.0f) {
            idx = 0;          we = make_float2(1.f, xv);
        } else if (xv > 1.0f) {
            idx = KNOTS - 1;  we = make_float2(1.f, xv - 1.0f);
        } else {
            idx = (int)floorf(xv * (float)(KNOTS - 1));
            if (idx > KNOTS - 2) idx = KNOTS - 2;
            float t  = (xv - (float)idx * hf) * (float)(KNOTS - 1);
            float t2 = t * t;
            float t3 = t2 * t;
            wi = make_float4(2.f * t3 - 3.f * t2 + 1.f,
                             (t3 - 2.f * t2 + t) * hf,
                             -2.f * t3 + 3.f * t2,
                             (t3 - t2) * hf);
        }

        unsigned m  = __ballot_sync(FULLMASK, ext);
        int nE = __popc(m);
        int baseE = 0, baseI = 0;
        if (lane == 0) {
            baseE = atomicAdd(&cnt[bl][half][0], nE);
            baseI = atomicAdd(&cnt[bl][half][1], 32 - nE);
        }
        baseE = __shfl_sync(FULLMASK, baseE, 0);
        baseI = __shfl_sync(FULLMASK, baseI, 0);
        unsigned ltm = (1u << lane) - 1u;
        int rankE = __popc(m & ltm);
        int rankI = lane - rankE;
        int rowbase = ((i << 6) + idx) << 6;   // (i*64+idx) * 64 uint2-units

        if (ext) {
            int s = baseE + rankE;
            eb[bl][half][s] = rowbase;
            ew[bl][half][s] = we;
        } else {
            int s = baseI + rankI;
            ib[bl][half][s] = rowbase;
            iw[bl][half][s] = wi;
        }
    }
    __syncthreads();

    // -------- Phase 2: gather + accumulate --------------------------------
    const int warp = tid >> 5;
    const int bl   = warp >> 1;
    const int half = warp & 1;
    const int nE = cnt[bl][half][0];
    const int nI = cnt[bl][half][1];

    const uint2* __restrict__ T = reinterpret_cast<const uint2*>(g_th);

    float4 acc = make_float4(0.f, 0.f, 0.f, 0.f);

    #pragma unroll 4
    for (int j = 0; j < nE; ++j) {
        int rb = eb[bl][half][j] + lane;
        uint2 v = __ldg(&T[rb]);           // ct quad (4 halfs)
        uint2 s = __ldg(&T[rb + 32]);      // dt quad
        float2 w = ew[bl][half][j];
        qfma(acc, v, w.x);
        qfma(acc, s, w.y);
    }

    #pragma unroll 2
    for (int j = 0; j < nI; ++j) {
        int rb = ib[bl][half][j] + lane;
        uint2 v0 = __ldg(&T[rb]);
        uint2 s0 = __ldg(&T[rb + 32]);
        uint2 v1 = __ldg(&T[rb + 64]);
        uint2 s1 = __ldg(&T[rb + 96]);
        float4 w = iw[bl][half][j];
        qfma(acc, v0, w.x);
        qfma(acc, s0, w.y);
        qfma(acc, v1, w.z);
        qfma(acc, s1, w.w);
    }

    // Combine i-halves; add bias; write.
    if (half) {
        part[bl][lane] = acc;
    }
    __syncthreads();
    if (!half) {
        float4 pv = part[bl][lane];
        float4 bb = __ldg(&reinterpret_cast<const float4*>(bias)[lane]);
        acc.x += pv.x + bb.x;
        acc.y += pv.y + bb.y;
        acc.z += pv.z + bb.z;
        acc.w += pv.w + bb.w;
        reinterpret_cast<float4*>(out)[(b0 + bl) * (D_OUTF / 4) + lane] = acc;
    }
}

// ---------------------------------------------------------------------------
// Launch
// ---------------------------------------------------------------------------
extern "C" void kernel_launch(void* const* d_in, const int* in_sizes, int n_in,
                              void* d_out, int out_size)
{
    const float* x      = (const float*)d_in[0];  // [4096,128]
    const float* coeffs = (const float*)d_in[1];  // [128,128,64]
    const float* bias   = (const float*)d_in[2];  // [128]
    const float* knots  = (const float*)d_in[3];  // [64]
    float* out = (float*)d_out;                   // [4096,128]

    kan_preprocess<<<D_INF, 512>>>(coeffs, knots);
    kan_main<<<NBATCH / BPB, 256>>>(x, bias, out);
}

// round 11
// speedup vs baseline: 2.2623x; 1.1168x over previous
#include <cuda_runtime.h>
#include <cuda_fp16.h>
#include <math.h>

#define D_INF   128
#define D_OUTF  128
#define KNOTS   64
#define NBATCH  4096
#define EPSF    1e-12f
#define BPB     4      // batches per block (2 warps per batch, i-halves)
#define FULLMASK 0xffffffffu

// Interleaved fp16 table: [i][k][ ct(128) | dt(128) ]  (512B per (i,k) pair)
__device__ __half g_th[D_INF * KNOTS * 2 * D_OUTF];

// ---------------------------------------------------------------------------
// Packed fp16 dot helpers. v/s quads are 4 halfs (one o-quad) in a uint2.
// Full dot computed in half2, flushed to fp32 acc once per call.
// ---------------------------------------------------------------------------
__device__ __forceinline__ __half2 h2(unsigned u) {
    return *reinterpret_cast<const __half2*>(&u);
}

__device__ __forceinline__ void dot_ext(float4& acc, uint2 v, uint2 s,
                                        uint2 w) {   // w = (w0w0, w1w1)
    __half2 p0 = __hmul2(h2(v.x), h2(w.x));
    p0 = __hfma2(h2(s.x), h2(w.y), p0);
    __half2 p1 = __hmul2(h2(v.y), h2(w.x));
    p1 = __hfma2(h2(s.y), h2(w.y), p1);
    float2 f0 = __half22float2(p0);
    float2 f1 = __half22float2(p1);
    acc.x += f0.x; acc.y += f0.y; acc.z += f1.x; acc.w += f1.y;
}

__device__ __forceinline__ void dot_int(float4& acc,
                                        uint2 v0, uint2 s0, uint2 v1, uint2 s1,
                                        uint4 w) {   // w = 4x (wi,wi) half2
    __half2 p0 = __hmul2(h2(v0.x), h2(w.x));
    p0 = __hfma2(h2(s0.x), h2(w.y), p0);
    p0 = __hfma2(h2(v1.x), h2(w.z), p0);
    p0 = __hfma2(h2(s1.x), h2(w.w), p0);
    __half2 p1 = __hmul2(h2(v0.y), h2(w.x));
    p1 = __hfma2(h2(s0.y), h2(w.y), p1);
    p1 = __hfma2(h2(v1.y), h2(w.z), p1);
    p1 = __hfma2(h2(s1.y), h2(w.w), p1);
    float2 f0 = __half22float2(p0);
    float2 f1 = __half22float2(p1);
    acc.x += f0.x; acc.y += f0.y; acc.z += f1.x; acc.w += f1.y;
}

// ---------------------------------------------------------------------------
// Kernel 1: PCHIP slopes + transpose into interleaved fp16 table.
// grid = 128 (i), block = 512 = (o:128, q:4); each thread owns 16 k's.
// All math in fp32; only the final store quantizes to fp16.
// ---------------------------------------------------------------------------
__global__ __launch_bounds__(512) void kan_preprocess(
    const float* __restrict__ coeffs,   // [D_OUT][D_IN][K]
    const float* __restrict__ knots)    // [K]
{
    __shared__ float ybuf[D_OUTF][KNOTS + 1];   // +1 pad
    __shared__ float h_s[KNOTS];
    __shared__ float rh_s[KNOTS];

    const int tid = threadIdx.x;
    const int i   = blockIdx.x;
    const int o   = tid & 127;
    const int q   = tid >> 7;

    if (tid < KNOTS - 1) {
        float h = knots[tid + 1] - knots[tid];
        h_s[tid]  = h;
        rh_s[tid] = 1.0f / (h + EPSF);
    }
    for (int j = tid; j < D_OUTF * KNOTS; j += 512) {
        int oo = j >> 6;
        int kk = j & (KNOTS - 1);
        ybuf[oo][kk] = coeffs[(oo * D_INF + i) * KNOTS + kk];
    }
    __syncthreads();

    const float* y = ybuf[o];
    __half* ct = g_th + (i * KNOTS) * (2 * D_OUTF) + o;
    __half* dt = ct + D_OUTF;
    const int k0 = q * 16;

    #pragma unroll
    for (int kk = 0; kk < 16; ++kk) {
        int k = k0 + kk;
        ct[k * 2 * D_OUTF] = __float2half(y[k]);
    }

    float del[17];
    #pragma unroll
    for (int kk = 0; kk < 17; ++kk) {
        int k = k0 - 1 + kk;
        del[kk] = (k >= 0 && k < KNOTS - 1) ? (y[k + 1] - y[k]) * rh_s[k] : 0.f;
    }

    #pragma unroll
    for (int kk = 0; kk < 16; ++kk) {
        int k = k0 + kk;
        if (k >= 1 && k <= KNOTS - 2) {
            float dprev = del[kk];
            float dcur  = del[kk + 1];
            float h0 = h_s[k - 1], h1 = h_s[k];
            float w1 = 2.f * h1 + h0;
            float w2 = h1 + 2.f * h0;
            float dpe = dprev + EPSF;
            float dce = dcur + EPSF;
            float num = (w1 + w2) * dpe * dce;
            float den = w1 * dce + w2 * dpe + EPSF * dpe * dce;
            float dd  = (dprev * dcur > 0.f) ? __fdividef(num, den) : 0.f;
            dt[k * 2 * D_OUTF] = __float2half(dd);
        }
    }

    if (k0 == 0) {
        float delta0 = del[1];
        float delta1 = del[2];
        float df = __fdividef((2.f * h_s[0] + h_s[1]) * delta0 - h_s[0] * delta1,
                              h_s[0] + h_s[1] + EPSF);
        df = (df * delta0 <= 0.f) ? 0.f : df;
        df = (fabsf(df) > 3.f * fabsf(delta0)) ? 3.f * delta0 : df;
        dt[0] = __float2half(df);
    }
    if (k0 == 48) {
        float delta62 = del[15];
        float delta61 = del[14];
        float dl = __fdividef((2.f * h_s[KNOTS - 2] + h_s[KNOTS - 3]) * delta62 -
                              h_s[KNOTS - 2] * delta61,
                              h_s[KNOTS - 2] + h_s[KNOTS - 3] + EPSF);
        dl = (dl * delta62 <= 0.f) ? 0.f : dl;
        dl = (fabsf(dl) > 3.f * fabsf(delta62)) ? 3.f * delta62 : dl;
        dt[(KNOTS - 1) * 2 * D_OUTF] = __float2half(dl);
    }
}

// ---------------------------------------------------------------------------
// Kernel 2: main evaluation. Compaction as before; per-i dots computed with
// packed HFMA2 (weights pre-broadcast into half2 in phase 1), flushed to the
// fp32 accumulator once per iteration. Row-pair (i,k) = 64 uint2 units:
// ct = [0,32), dt = [32,64), next knot at +64.
// ---------------------------------------------------------------------------
__global__ __launch_bounds__(256) void kan_main(
    const float* __restrict__ x,      // [B][D_IN]
    const float* __restrict__ bias,   // [D_OUT]
    float* __restrict__ out)          // [B][D_OUT]
{
    __shared__ int   eb[BPB][2][64];     // ext row base (uint2 units)
    __shared__ uint2 ew[BPB][2][64];     // ext weights: 2x (w,w) half2
    __shared__ int   ib[BPB][2][64];     // interior row base
    __shared__ uint4 iw[BPB][2][64];     // interior weights: 4x (w,w) half2
    __shared__ int   cnt[BPB][2][2];     // [bl][half][ext|int]
    __shared__ float4 part[BPB][32];

    const int tid  = threadIdx.x;
    const int lane = tid & 31;
    const int b0   = blockIdx.x * BPB;
    const float hf = 1.0f / (float)(KNOTS - 1);

    if (tid < BPB * 2 * 2) ((int*)cnt)[tid] = 0;
    __syncthreads();

    // -------- Phase 1: classify + compact ---------------------------------
    for (int p = tid; p < BPB * D_INF; p += 256) {
        int bl   = p >> 7;
        int i    = p & (D_INF - 1);
        int half = i >> 6;
        float xv = x[(b0 + bl) * D_INF + i];

        bool ext = (xv < 0.0f) | (xv > 1.0f);
        int idx;
        float w0, w1, w2, w3;
        if (xv < 0.0f) {
            idx = 0;          w0 = 1.f; w1 = xv;        w2 = 0.f; w3 = 0.f;
        } else if (xv > 1.0f) {
            idx = KNOTS - 1;  w0 = 1.f; w1 = xv - 1.0f; w2 = 0.f; w3 = 0.f;
        } else {
            idx = (int)floorf(xv * (float)(KNOTS - 1));
            if (idx > KNOTS - 2) idx = KNOTS - 2;
            float t  = (xv - (float)idx * hf) * (float)(KNOTS - 1);
            float t2 = t * t;
            float t3 = t2 * t;
            w0 = 2.f * t3 - 3.f * t2 + 1.f;
            w1 = (t3 - 2.f * t2 + t) * hf;
            w2 = -2.f * t3 + 3.f * t2;
            w3 = (t3 - t2) * hf;
        }
        __half2 h0 = __float2half2_rn(w0);
        __half2 h1 = __float2half2_rn(w1);
        __half2 h2w = __float2half2_rn(w2);
        __half2 h3 = __float2half2_rn(w3);

        unsigned m  = __ballot_sync(FULLMASK, ext);
        int nE = __popc(m);
        int baseE = 0, baseI = 0;
        if (lane == 0) {
            baseE = atomicAdd(&cnt[bl][half][0], nE);
            baseI = atomicAdd(&cnt[bl][half][1], 32 - nE);
        }
        baseE = __shfl_sync(FULLMASK, baseE, 0);
        baseI = __shfl_sync(FULLMASK, baseI, 0);
        unsigned ltm = (1u << lane) - 1u;
        int rankE = __popc(m & ltm);
        int rankI = lane - rankE;
        int rowbase = ((i << 6) + idx) << 6;   // (i*64+idx) * 64 uint2-units

        if (ext) {
            int s = baseE + rankE;
            eb[bl][half][s] = rowbase;
            ew[bl][half][s] = make_uint2(*(unsigned*)&h0, *(unsigned*)&h1);
        } else {
            int s = baseI + rankI;
            ib[bl][half][s] = rowbase;
            iw[bl][half][s] = make_uint4(*(unsigned*)&h0, *(unsigned*)&h1,
                                         *(unsigned*)&h2w, *(unsigned*)&h3);
        }
    }
    __syncthreads();

    // -------- Phase 2: gather + accumulate --------------------------------
    const int warp = tid >> 5;
    const int bl   = warp >> 1;
    const int half = warp & 1;
    const int nE = cnt[bl][half][0];
    const int nI = cnt[bl][half][1];

    const uint2* __restrict__ T = reinterpret_cast<const uint2*>(g_th);

    float4 acc = make_float4(0.f, 0.f, 0.f, 0.f);

    #pragma unroll 4
    for (int j = 0; j < nE; ++j) {
        int rb = eb[bl][half][j] + lane;
        uint2 v = __ldg(&T[rb]);           // ct quad (4 halfs)
        uint2 s = __ldg(&T[rb + 32]);      // dt quad
        dot_ext(acc, v, s, ew[bl][half][j]);
    }

    #pragma unroll 2
    for (int j = 0; j < nI; ++j) {
        int rb = ib[bl][half][j] + lane;
        uint2 v0 = __ldg(&T[rb]);
        uint2 s0 = __ldg(&T[rb + 32]);
        uint2 v1 = __ldg(&T[rb + 64]);
        uint2 s1 = __ldg(&T[rb + 96]);
        dot_int(acc, v0, s0, v1, s1, iw[bl][half][j]);
    }

    // Combine i-halves; add bias; write.
    if (half) {
        part[bl][lane] = acc;
    }
    __syncthreads();
    if (!half) {
        float4 pv = part[bl][lane];
        float4 bb = __ldg(&reinterpret_cast<const float4*>(bias)[lane]);
        acc.x += pv.x + bb.x;
        acc.y += pv.y + bb.y;
        acc.z += pv.z + bb.z;
        acc.w += pv.w + bb.w;
        reinterpret_cast<float4*>(out)[(b0 + bl) * (D_OUTF / 4) + lane] = acc;
    }
}

// ---------------------------------------------------------------------------
// Launch
// ---------------------------------------------------------------------------
extern "C" void kernel_launch(void* const* d_in, const int* in_sizes, int n_in,
                              void* d_out, int out_size)
{
    const float* x      = (const float*)d_in[0];  // [4096,128]
    const float* coeffs = (const float*)d_in[1];  // [128,128,64]
    const float* bias   = (const float*)d_in[2];  // [128]
    const float* knots  = (const float*)d_in[3];  // [64]
    float* out = (float*)d_out;                   // [4096,128]

    kan_preprocess<<<D_INF, 512>>>(coeffs, knots);
    kan_main<<<NBATCH / BPB, 256>>>(x, bias, out);
}